// round 7
// baseline (speedup 1.0000x reference)
#include <cuda_runtime.h>
#include <cuda_bf16.h>

// Cubic B-spline eval via per-span cubic polynomials + DIRECT bin records.
//
//  1. sort_kernel:   warp-per-element rank sort of 1024 knots -> g_ts
//  2. setup2_kernel: blocks 0-3:  span records g_rec[i] = {t, c0, c1, c3c2}
//                    blocks 4-35: g_binrec[8192]: clean bin -> full record of
//                    its unique span; dirty bin -> {+inf, span_idx}
//  3. eval_kernel:   152 CTAs x 1024 thr, 144KB dynamic shared.
//     fast path: 1 FFMA (bin) + 1 LDS.128 + 3 FFMA Horner per point.

#define KNOTS 1024
#define DEG   3
#define NBINS 8192
#define LOK   3        // first valid knot index (domain = (ts[3], ts[1020]))
#define HIK   1020     // last valid knot index; valid spans i in [3, 1019]
#define DIRTY_BITS 0x7F800000u   // +inf marker in record.x

__device__ float  g_ts[KNOTS];
__device__ float4 g_rec[KNOTS];      // {ts[i], c0, c1, bf16 c3<<16 | bf16 c2}
__device__ float4 g_binrec[NBINS];   // direct per-bin records (or dirty marker)

// ---------------------------------------------------------------------------
// 1. Rank sort, warp-per-element (stable: ties broken by original index).
// ---------------------------------------------------------------------------
__global__ void __launch_bounds__(256)
sort_kernel(const float* __restrict__ knots) {
    __shared__ float s[KNOTS];
    int t = threadIdx.x;
    {
        float4* s4 = (float4*)s;
        const float4* k4 = (const float4*)knots;
        for (int m = t; m < KNOTS / 4; m += 256) s4[m] = k4[m];
    }
    __syncthreads();

    int wid  = t >> 5;
    int lane = t & 31;
    int i    = blockIdx.x * 8 + wid;
    float v  = s[i];
    int cnt  = 0;
    #pragma unroll
    for (int k = 0; k < KNOTS / 32; ++k) {
        int m = (k << 5) + lane;
        float a = s[m];
        cnt += (a < v) || (a == v && m < i);
    }
    cnt = __reduce_add_sync(0xffffffffu, cnt);
    if (lane == 0) g_ts[cnt] = v;
}

// ---------------------------------------------------------------------------
// Span record builder: symbolic de Boor on cubic coefficients in u = x-ts[i].
// ---------------------------------------------------------------------------
__device__ __forceinline__ float4 make_record(int i, const float* __restrict__ ctrl) {
    float T[7];
    #pragma unroll
    for (int m = 0; m < 7; ++m) T[m] = g_ts[i - 3 + m];
    float ti = T[3];
    float d[4][4];
    #pragma unroll
    for (int j = 0; j < 4; ++j) {
        d[j][0] = ctrl[i - 3 + j];
        d[j][1] = 0.f; d[j][2] = 0.f; d[j][3] = 0.f;
    }
    #pragma unroll
    for (int r = 1; r <= DEG; ++r) {
        #pragma unroll
        for (int j = DEG; j >= 1; --j) {
            if (j < r) continue;
            float tl = T[j];            // ts[i+j-3]
            float tr = T[j + 4 - r];    // ts[i+j+1-r]
            float den = tr - tl;
            float a1 = (den != 0.f) ? (1.f / den) : 0.f;
            float a0 = (ti - tl) * a1;
            float e[4];
            #pragma unroll
            for (int m = 0; m < 4; ++m) e[m] = d[j][m] - d[j - 1][m];
            #pragma unroll
            for (int m = 0; m < 4; ++m) d[j][m] = d[j - 1][m] + a0 * e[m];
            #pragma unroll
            for (int m = 1; m < 4; ++m) d[j][m] += a1 * e[m - 1];
        }
    }
    unsigned c2b = (unsigned)__bfloat16_as_ushort(__float2bfloat16(d[3][2]));
    unsigned c3b = (unsigned)__bfloat16_as_ushort(__float2bfloat16(d[3][3]));
    float4 R;
    R.x = ti; R.y = d[3][0]; R.z = d[3][1];
    R.w = __uint_as_float((c3b << 16) | c2b);
    return R;
}

// ---------------------------------------------------------------------------
// 2. Fused setup. Blocks 0-3: g_rec. Blocks 4-35: g_binrec (reads only g_ts
//    and ctrl — recomputes records locally, so no cross-block ordering needed).
// ---------------------------------------------------------------------------
__global__ void setup2_kernel(const float* __restrict__ ctrl) {
    if (blockIdx.x < 4) {
        int i = blockIdx.x * 256 + threadIdx.x;      // 0..1023
        float4 R = make_float4(g_ts[i], 0.f, 0.f, 0.f);
        if (i >= LOK && i <= HIK) R = make_record(i, ctrl);
        g_rec[i] = R;
    } else {
        int b = (blockIdx.x - 4) * 256 + threadIdx.x;  // 0..8191
        float lo = g_ts[LOK], hi = g_ts[HIK];
        float w  = (hi - lo) / (float)NBINS;
        float e0 = fmaf((float)b,       w, lo);
        float e1 = fmaf((float)(b + 1), w, lo);
        int s0, s1;
        #pragma unroll
        for (int pass = 0; pass < 2; ++pass) {
            float e = pass ? e1 : e0;
            int loI = 0, hiI = KNOTS;
            while (loI < hiI) {
                int mid = (loI + hiI) >> 1;
                if (g_ts[mid] < e) loI = mid + 1; else hiI = mid;
            }
            int s = loI - 1;
            if (s < LOK) s = LOK;
            if (s > HIK - 1) s = HIK - 1;
            if (pass) s1 = s; else s0 = s;
        }
        float4 R;
        if (s0 == s1) {
            R = make_record(s0, ctrl);               // clean: direct record
        } else {
            R.x = __uint_as_float(DIRTY_BITS);       // dirty: marker + index
            R.y = __uint_as_float((unsigned)s0);
            R.z = 0.f; R.w = 0.f;
        }
        g_binrec[b] = R;
    }
}

// ---------------------------------------------------------------------------
// 3. Eval. Shared layout (dynamic): B[8192] float4, rec[1024] float4.
// ---------------------------------------------------------------------------
extern __shared__ float4 s_dyn[];

__device__ __forceinline__ float horner(float4 R, float x) {
    float u = x - R.x;
    unsigned pw = __float_as_uint(R.w);
    float c2 = __uint_as_float(pw << 16);
    float c3 = __uint_as_float(pw & 0xFFFF0000u);
    return fmaf(fmaf(fmaf(c3, u, c2), u, R.z), u, R.y);
}

__device__ __forceinline__ float eval_one(float x,
                                          const float4* __restrict__ B,
                                          const float4* __restrict__ rec,
                                          float nlo_invw, float invw) {
    int b = (int)fmaf(x, invw, nlo_invw);
    float4 R = B[b];
    if (__float_as_uint(R.x) == DIRTY_BITS) {        // dirty: exact strict scan
        int i = (int)__float_as_uint(R.y);
        while (i < HIK - 1 && x > rec[i + 1].x) ++i;
        R = rec[i];
        while (i > LOK && x <= R.x) { --i; R = rec[i]; }
    }
    return horner(R, x);
}

__global__ void __launch_bounds__(1024)
eval_kernel(const float4* __restrict__ x4, float4* __restrict__ out4, int n4,
            const float* __restrict__ x_tail, float* __restrict__ out_tail,
            int n_tail) {
    float4* B   = s_dyn;                 // [NBINS]
    float4* rec = s_dyn + NBINS;         // [KNOTS]

    int t = threadIdx.x;
    for (int m = t; m < NBINS; m += 1024) B[m] = g_binrec[m];
    for (int m = t; m < KNOTS; m += 1024) rec[m] = g_rec[m];
    __syncthreads();

    float lo   = rec[LOK].x;
    float hi   = rec[HIK].x;
    float invw = (float)NBINS / (hi - lo);
    float nlo_invw = -lo * invw;

    int stride = gridDim.x * 1024;
    for (int idx = blockIdx.x * 1024 + t; idx < n4; idx += stride) {
        float4 xv = x4[idx];
        float4 r;
        r.x = eval_one(xv.x, B, rec, nlo_invw, invw);
        r.y = eval_one(xv.y, B, rec, nlo_invw, invw);
        r.z = eval_one(xv.z, B, rec, nlo_invw, invw);
        r.w = eval_one(xv.w, B, rec, nlo_invw, invw);
        out4[idx] = r;
    }
    if (blockIdx.x == 0 && t < n_tail) {
        out_tail[t] = eval_one(x_tail[t], B, rec, nlo_invw, invw);
    }
}

// ---------------------------------------------------------------------------
extern "C" void kernel_launch(void* const* d_in, const int* in_sizes, int n_in,
                              void* d_out, int out_size) {
    const float* x     = (const float*)d_in[0];   // [N_PTS]
    const float* knots = (const float*)d_in[1];   // [1024]
    const float* ctrl  = (const float*)d_in[2];   // [1021]
    float* out = (float*)d_out;

    int n  = in_sizes[0];
    int n4 = n >> 2;
    int n_tail = n & 3;

    const int SMEM = (NBINS + KNOTS) * (int)sizeof(float4);   // 147456 B
    static int smem_set = 0;   // attribute is sticky; harmless to reset
    if (!smem_set) {
        cudaFuncSetAttribute(eval_kernel,
                             cudaFuncAttributeMaxDynamicSharedMemorySize, SMEM);
        smem_set = 1;
    }

    sort_kernel<<<KNOTS / 8, 256>>>(knots);
    setup2_kernel<<<36, 256>>>(ctrl);

    eval_kernel<<<152, 1024, SMEM>>>((const float4*)x, (float4*)out, n4,
                                     x + (size_t)n4 * 4, out + (size_t)n4 * 4,
                                     n_tail);
}

// round 8
// speedup vs baseline: 1.0903x; 1.0903x over previous
#include <cuda_runtime.h>
#include <cuda_bf16.h>

// Cubic B-spline eval via per-span cubic polynomials + DIRECT bin records.
//
//  1. sort_kernel:   warp-per-element rank sort (coalesced LDG, no smem)
//  2. setup2_kernel: blocks 0-3:  span records g_rec[i] = {t, c0, c1, c3c2}
//                    blocks 4-27: g_binrec[6144]: clean bin -> full record of
//                    its unique span; dirty bin -> {+inf, span_idx}
//  3. eval_kernel:   grid 304 x 1024 thr, 112KB dynamic shared -> 2 CTAs/SM,
//                    64 warps/SM. Fast path: 1 FFMA (bin) + 1 LDS.128 +
//                    3 FFMA Horner per point.

#define KNOTS 1024
#define DEG   3
#define NBINS 6144
#define LOK   3        // first valid knot index (domain = (ts[3], ts[1020]))
#define HIK   1020     // last valid knot index; valid spans i in [3, 1019]
#define DIRTY_BITS 0x7F800000u   // +inf marker in record.x

__device__ float  g_ts[KNOTS];
__device__ float4 g_rec[KNOTS];      // {ts[i], c0, c1, bf16 c3<<16 | bf16 c2}
__device__ float4 g_binrec[NBINS];   // direct per-bin records (or dirty marker)

// ---------------------------------------------------------------------------
// 1. Rank sort, warp-per-element, no shared: lane reads knots[k*32+lane]
//    (coalesced, L1-hit after first line). Stable rank via index tiebreak.
//    Grid 32 x 1024: warp w of block b ranks element b*32 + w.
// ---------------------------------------------------------------------------
__global__ void __launch_bounds__(1024)
sort_kernel(const float* __restrict__ knots) {
    int t    = threadIdx.x;
    int wid  = t >> 5;
    int lane = t & 31;
    int i    = blockIdx.x * 32 + wid;
    float v  = __ldg(&knots[i]);
    int cnt  = 0;
    #pragma unroll
    for (int k = 0; k < KNOTS / 32; ++k) {
        int m = (k << 5) + lane;
        float a = __ldg(&knots[m]);
        cnt += (a < v) || (a == v && m < i);
    }
    cnt = __reduce_add_sync(0xffffffffu, cnt);
    if (lane == 0) g_ts[cnt] = v;
}

// ---------------------------------------------------------------------------
// Span record builder: symbolic de Boor on cubic coefficients in u = x-ts[i].
// ---------------------------------------------------------------------------
__device__ __forceinline__ float4 make_record(int i, const float* __restrict__ ctrl) {
    float T[7];
    #pragma unroll
    for (int m = 0; m < 7; ++m) T[m] = g_ts[i - 3 + m];
    float ti = T[3];
    float d[4][4];
    #pragma unroll
    for (int j = 0; j < 4; ++j) {
        d[j][0] = ctrl[i - 3 + j];
        d[j][1] = 0.f; d[j][2] = 0.f; d[j][3] = 0.f;
    }
    #pragma unroll
    for (int r = 1; r <= DEG; ++r) {
        #pragma unroll
        for (int j = DEG; j >= 1; --j) {
            if (j < r) continue;
            float tl = T[j];            // ts[i+j-3]
            float tr = T[j + 4 - r];    // ts[i+j+1-r]
            float den = tr - tl;
            float a1 = (den != 0.f) ? (1.f / den) : 0.f;
            float a0 = (ti - tl) * a1;
            float e[4];
            #pragma unroll
            for (int m = 0; m < 4; ++m) e[m] = d[j][m] - d[j - 1][m];
            #pragma unroll
            for (int m = 0; m < 4; ++m) d[j][m] = d[j - 1][m] + a0 * e[m];
            #pragma unroll
            for (int m = 1; m < 4; ++m) d[j][m] += a1 * e[m - 1];
        }
    }
    unsigned c2b = (unsigned)__bfloat16_as_ushort(__float2bfloat16(d[3][2]));
    unsigned c3b = (unsigned)__bfloat16_as_ushort(__float2bfloat16(d[3][3]));
    float4 R;
    R.x = ti; R.y = d[3][0]; R.z = d[3][1];
    R.w = __uint_as_float((c3b << 16) | c2b);
    return R;
}

// ---------------------------------------------------------------------------
// 2. Fused setup. Blocks 0-3: g_rec. Blocks 4-27: g_binrec (reads only g_ts
//    and ctrl — recomputes records locally, no cross-block ordering needed).
// ---------------------------------------------------------------------------
__global__ void setup2_kernel(const float* __restrict__ ctrl) {
    if (blockIdx.x < 4) {
        int i = blockIdx.x * 256 + threadIdx.x;      // 0..1023
        float4 R = make_float4(g_ts[i], 0.f, 0.f, 0.f);
        if (i >= LOK && i <= HIK) R = make_record(i, ctrl);
        g_rec[i] = R;
    } else {
        int b = (blockIdx.x - 4) * 256 + threadIdx.x;  // 0..6143
        float lo = g_ts[LOK], hi = g_ts[HIK];
        float w  = (hi - lo) / (float)NBINS;
        float e0 = fmaf((float)b,       w, lo);
        float e1 = fmaf((float)(b + 1), w, lo);
        int s0, s1;
        #pragma unroll
        for (int pass = 0; pass < 2; ++pass) {
            float e = pass ? e1 : e0;
            int loI = 0, hiI = KNOTS;
            while (loI < hiI) {
                int mid = (loI + hiI) >> 1;
                if (g_ts[mid] < e) loI = mid + 1; else hiI = mid;
            }
            int s = loI - 1;
            if (s < LOK) s = LOK;
            if (s > HIK - 1) s = HIK - 1;
            if (pass) s1 = s; else s0 = s;
        }
        float4 R;
        if (s0 == s1) {
            R = make_record(s0, ctrl);               // clean: direct record
        } else {
            R.x = __uint_as_float(DIRTY_BITS);       // dirty: marker + index
            R.y = __uint_as_float((unsigned)s0);
            R.z = 0.f; R.w = 0.f;
        }
        g_binrec[b] = R;
    }
}

// ---------------------------------------------------------------------------
// 3. Eval. Shared layout (dynamic): B[6144] float4, rec[1024] float4. 112KB.
// ---------------------------------------------------------------------------
extern __shared__ float4 s_dyn[];

__device__ __forceinline__ float horner(float4 R, float x) {
    float u = x - R.x;
    unsigned pw = __float_as_uint(R.w);
    float c2 = __uint_as_float(pw << 16);
    float c3 = __uint_as_float(pw & 0xFFFF0000u);
    return fmaf(fmaf(fmaf(c3, u, c2), u, R.z), u, R.y);
}

__device__ __forceinline__ float eval_one(float x,
                                          const float4* __restrict__ B,
                                          const float4* __restrict__ rec,
                                          float nlo_invw, float invw) {
    int b = (int)fmaf(x, invw, nlo_invw);
    float4 R = B[b];
    if (__float_as_uint(R.x) == DIRTY_BITS) {        // dirty: exact strict scan
        int i = (int)__float_as_uint(R.y);
        while (i < HIK - 1 && x > rec[i + 1].x) ++i;
        R = rec[i];
        while (i > LOK && x <= R.x) { --i; R = rec[i]; }
    }
    return horner(R, x);
}

__global__ void __launch_bounds__(1024, 2)
eval_kernel(const float4* __restrict__ x4, float4* __restrict__ out4, int n4,
            const float* __restrict__ x_tail, float* __restrict__ out_tail,
            int n_tail) {
    float4* B   = s_dyn;                 // [NBINS]
    float4* rec = s_dyn + NBINS;         // [KNOTS]

    int t = threadIdx.x;
    for (int m = t; m < NBINS; m += 1024) B[m] = g_binrec[m];
    for (int m = t; m < KNOTS; m += 1024) rec[m] = g_rec[m];
    __syncthreads();

    float lo   = rec[LOK].x;
    float hi   = rec[HIK].x;
    float invw = (float)NBINS / (hi - lo);
    float nlo_invw = -lo * invw;

    int stride = gridDim.x * 1024;
    for (int idx = blockIdx.x * 1024 + t; idx < n4; idx += stride) {
        float4 xv = x4[idx];
        float4 r;
        r.x = eval_one(xv.x, B, rec, nlo_invw, invw);
        r.y = eval_one(xv.y, B, rec, nlo_invw, invw);
        r.z = eval_one(xv.z, B, rec, nlo_invw, invw);
        r.w = eval_one(xv.w, B, rec, nlo_invw, invw);
        out4[idx] = r;
    }
    if (blockIdx.x == 0 && t < n_tail) {
        out_tail[t] = eval_one(x_tail[t], B, rec, nlo_invw, invw);
    }
}

// ---------------------------------------------------------------------------
extern "C" void kernel_launch(void* const* d_in, const int* in_sizes, int n_in,
                              void* d_out, int out_size) {
    const float* x     = (const float*)d_in[0];   // [N_PTS]
    const float* knots = (const float*)d_in[1];   // [1024]
    const float* ctrl  = (const float*)d_in[2];   // [1021]
    float* out = (float*)d_out;

    int n  = in_sizes[0];
    int n4 = n >> 2;
    int n_tail = n & 3;

    const int SMEM = (NBINS + KNOTS) * (int)sizeof(float4);   // 114688 B
    static int smem_set = 0;
    if (!smem_set) {
        cudaFuncSetAttribute(eval_kernel,
                             cudaFuncAttributeMaxDynamicSharedMemorySize, SMEM);
        smem_set = 1;
    }

    sort_kernel<<<KNOTS / 32, 1024>>>(knots);   // 32 blocks, warp-per-element
    setup2_kernel<<<28, 256>>>(ctrl);           // 4 record blocks + 24 bin blocks

    eval_kernel<<<304, 1024, SMEM>>>((const float4*)x, (float4*)out, n4,
                                     x + (size_t)n4 * 4, out + (size_t)n4 * 4,
                                     n_tail);
}